// round 4
// baseline (speedup 1.0000x reference)
#include <cuda_runtime.h>
#include <math.h>
#include <stdint.h>

#define BB 2
#define SEQ 2048
#define DMODEL 1024
#define NH 16
#define HD 64
#define QKV_ELEMS (BB * SEQ * DMODEL)

// Scratch (no allocations allowed)
__device__ float g_q[QKV_ELEMS];
__device__ float g_k[QKV_ELEMS];
__device__ float g_v[QKV_ELEMS];
__device__ float g_ctx[QKV_ELEMS];

__device__ __forceinline__ uint32_t f2tf(float x) {
    uint32_t r;
    asm("cvt.rna.tf32.f32 %0, %1;" : "=r"(r) : "f"(x));
    return r;
}

__device__ __forceinline__ void mma8(float* c, const uint32_t* a, const uint32_t* b) {
    asm volatile(
        "mma.sync.aligned.m16n8k8.row.col.f32.tf32.tf32.f32 "
        "{%0,%1,%2,%3},{%4,%5,%6,%7},{%8,%9},{%0,%1,%2,%3};"
        : "+f"(c[0]), "+f"(c[1]), "+f"(c[2]), "+f"(c[3])
        : "r"(a[0]), "r"(a[1]), "r"(a[2]), "r"(a[3]), "r"(b[0]), "r"(b[1]));
}

// ---------------------------------------------------------------------------
// Proj GEMM (NN): C = A[M,K] @ B[K,N] + bias. 128 threads, CTA 128x128,
// warp tile 64x64 (2x2 warps), BK=16, double-buffered smem, tf32 mma.
// ---------------------------------------------------------------------------
__global__ __launch_bounds__(128) void proj_tf32(
    const float* __restrict__ A, const float* __restrict__ B,
    const float* __restrict__ bias, float* __restrict__ C,
    int M, int N, int K)
{
    __shared__ uint32_t As[2][128][20];   // [m][k], stride 20 == 4 mod 32
    __shared__ uint32_t Bs[2][16][136];   // [k][n], stride 136 == 8 mod 32

    const int tid = threadIdx.x;
    const int lane = tid & 31, wid = tid >> 5;
    const int warpM = wid >> 1, warpN = wid & 1;
    const int gp = lane >> 2, tig = lane & 3;
    const int rowBase = blockIdx.y * 128, colBase = blockIdx.x * 128;

    const float* aRow = A + (size_t)(rowBase + tid) * K;
    const int bkk = tid >> 5, bn4 = tid & 31;

    float4 aR[4], bR[4];
#pragma unroll
    for (int i = 0; i < 4; i++) aR[i] = *(const float4*)(aRow + i * 4);
#pragma unroll
    for (int i = 0; i < 4; i++)
        bR[i] = *(const float4*)(B + (size_t)(bkk + i * 4) * N + colBase + bn4 * 4);

    float acc[4][8][4];
#pragma unroll
    for (int t = 0; t < 4; t++)
#pragma unroll
        for (int j = 0; j < 8; j++)
#pragma unroll
            for (int q = 0; q < 4; q++) acc[t][j][q] = 0.0f;

    // stage buffer 0
#pragma unroll
    for (int i = 0; i < 4; i++) {
        uint32_t* ap = &As[0][tid][i * 4];
        ap[0] = f2tf(aR[i].x); ap[1] = f2tf(aR[i].y);
        ap[2] = f2tf(aR[i].z); ap[3] = f2tf(aR[i].w);
        uint32_t* bp = &Bs[0][bkk + i * 4][bn4 * 4];
        bp[0] = f2tf(bR[i].x); bp[1] = f2tf(bR[i].y);
        bp[2] = f2tf(bR[i].z); bp[3] = f2tf(bR[i].w);
    }
    __syncthreads();

    const int KT = K / 16;
    for (int kt = 0; kt < KT; ++kt) {
        const int buf = kt & 1;
        if (kt + 1 < KT) {
            const int k0 = (kt + 1) * 16;
#pragma unroll
            for (int i = 0; i < 4; i++) aR[i] = *(const float4*)(aRow + k0 + i * 4);
#pragma unroll
            for (int i = 0; i < 4; i++)
                bR[i] = *(const float4*)(B + (size_t)(k0 + bkk + i * 4) * N + colBase + bn4 * 4);
        }

#pragma unroll
        for (int ks = 0; ks < 2; ++ks) {
            uint32_t a[4][4], b[8][2];
#pragma unroll
            for (int t = 0; t < 4; t++) {
                int r = warpM * 64 + t * 16 + gp;
                a[t][0] = As[buf][r][ks * 8 + tig];
                a[t][1] = As[buf][r + 8][ks * 8 + tig];
                a[t][2] = As[buf][r][ks * 8 + tig + 4];
                a[t][3] = As[buf][r + 8][ks * 8 + tig + 4];
            }
#pragma unroll
            for (int j = 0; j < 8; j++) {
                int n = warpN * 64 + j * 8 + gp;
                b[j][0] = Bs[buf][ks * 8 + tig][n];
                b[j][1] = Bs[buf][ks * 8 + tig + 4][n];
            }
#pragma unroll
            for (int t = 0; t < 4; t++)
#pragma unroll
                for (int j = 0; j < 8; j++)
                    mma8(acc[t][j], a[t], b[j]);
        }

        if (kt + 1 < KT) {
            const int nb = buf ^ 1;
#pragma unroll
            for (int i = 0; i < 4; i++) {
                uint32_t* ap = &As[nb][tid][i * 4];
                ap[0] = f2tf(aR[i].x); ap[1] = f2tf(aR[i].y);
                ap[2] = f2tf(aR[i].z); ap[3] = f2tf(aR[i].w);
                uint32_t* bp = &Bs[nb][bkk + i * 4][bn4 * 4];
                bp[0] = f2tf(bR[i].x); bp[1] = f2tf(bR[i].y);
                bp[2] = f2tf(bR[i].z); bp[3] = f2tf(bR[i].w);
            }
        }
        __syncthreads();
    }

#pragma unroll
    for (int t = 0; t < 4; t++) {
#pragma unroll
        for (int j = 0; j < 8; j++) {
            int row = rowBase + warpM * 64 + t * 16 + gp;
            int col = colBase + warpN * 64 + j * 8 + 2 * tig;
            float2 bb = *(const float2*)&bias[col];
            float2 r0, r1;
            r0.x = acc[t][j][0] + bb.x; r0.y = acc[t][j][1] + bb.y;
            r1.x = acc[t][j][2] + bb.x; r1.y = acc[t][j][3] + bb.y;
            *(float2*)&C[(size_t)row * N + col] = r0;
            *(float2*)&C[(size_t)(row + 8) * N + col] = r1;
        }
    }
}

// ---------------------------------------------------------------------------
// Scores: S = (0.125*Q) @ K^T per (b,h). CTA 128x128, warp 64x64, BK=16,
// double-buffered. Q,K rows are K-major in gmem (stride DMODEL).
// ---------------------------------------------------------------------------
__global__ __launch_bounds__(128) void scores_tf32(float* __restrict__ attn)
{
    __shared__ uint32_t Qs[2][128][20];
    __shared__ uint32_t Ks[2][128][20];   // [n][k]

    const int tid = threadIdx.x;
    const int lane = tid & 31, wid = tid >> 5;
    const int warpM = wid >> 1, warpN = wid & 1;
    const int gp = lane >> 2, tig = lane & 3;
    const int z = blockIdx.z, b = z >> 4, h = z & 15;
    const int rowBase = blockIdx.y * 128, colBase = blockIdx.x * 128;

    const float* qRow = g_q + (size_t)(b * SEQ + rowBase + tid) * DMODEL + h * HD;
    const float* kRow = g_k + (size_t)(b * SEQ + colBase + tid) * DMODEL + h * HD;

    float4 qR[4], kR[4];
#pragma unroll
    for (int i = 0; i < 4; i++) { qR[i] = *(const float4*)(qRow + i * 4); kR[i] = *(const float4*)(kRow + i * 4); }

    float acc[4][8][4];
#pragma unroll
    for (int t = 0; t < 4; t++)
#pragma unroll
        for (int j = 0; j < 8; j++)
#pragma unroll
            for (int q = 0; q < 4; q++) acc[t][j][q] = 0.0f;

#pragma unroll
    for (int i = 0; i < 4; i++) {
        uint32_t* qp = &Qs[0][tid][i * 4];
        qp[0] = f2tf(qR[i].x * 0.125f); qp[1] = f2tf(qR[i].y * 0.125f);
        qp[2] = f2tf(qR[i].z * 0.125f); qp[3] = f2tf(qR[i].w * 0.125f);
        uint32_t* kp = &Ks[0][tid][i * 4];
        kp[0] = f2tf(kR[i].x); kp[1] = f2tf(kR[i].y);
        kp[2] = f2tf(kR[i].z); kp[3] = f2tf(kR[i].w);
    }
    __syncthreads();

    const int KT = HD / 16;   // 4
    for (int kt = 0; kt < KT; ++kt) {
        const int buf = kt & 1;
        if (kt + 1 < KT) {
            const int k0 = (kt + 1) * 16;
#pragma unroll
            for (int i = 0; i < 4; i++) {
                qR[i] = *(const float4*)(qRow + k0 + i * 4);
                kR[i] = *(const float4*)(kRow + k0 + i * 4);
            }
        }

#pragma unroll
        for (int ks = 0; ks < 2; ++ks) {
            uint32_t a[4][4], bfr[8][2];
#pragma unroll
            for (int t = 0; t < 4; t++) {
                int r = warpM * 64 + t * 16 + gp;
                a[t][0] = Qs[buf][r][ks * 8 + tig];
                a[t][1] = Qs[buf][r + 8][ks * 8 + tig];
                a[t][2] = Qs[buf][r][ks * 8 + tig + 4];
                a[t][3] = Qs[buf][r + 8][ks * 8 + tig + 4];
            }
#pragma unroll
            for (int j = 0; j < 8; j++) {
                int n = warpN * 64 + j * 8 + gp;
                bfr[j][0] = Ks[buf][n][ks * 8 + tig];
                bfr[j][1] = Ks[buf][n][ks * 8 + tig + 4];
            }
#pragma unroll
            for (int t = 0; t < 4; t++)
#pragma unroll
                for (int j = 0; j < 8; j++)
                    mma8(acc[t][j], a[t], bfr[j]);
        }

        if (kt + 1 < KT) {
            const int nb = buf ^ 1;
#pragma unroll
            for (int i = 0; i < 4; i++) {
                uint32_t* qp = &Qs[nb][tid][i * 4];
                qp[0] = f2tf(qR[i].x * 0.125f); qp[1] = f2tf(qR[i].y * 0.125f);
                qp[2] = f2tf(qR[i].z * 0.125f); qp[3] = f2tf(qR[i].w * 0.125f);
                uint32_t* kp = &Ks[nb][tid][i * 4];
                kp[0] = f2tf(kR[i].x); kp[1] = f2tf(kR[i].y);
                kp[2] = f2tf(kR[i].z); kp[3] = f2tf(kR[i].w);
            }
        }
        __syncthreads();
    }

    float* Cb = attn + (size_t)z * SEQ * SEQ;
#pragma unroll
    for (int t = 0; t < 4; t++) {
#pragma unroll
        for (int j = 0; j < 8; j++) {
            int row = rowBase + warpM * 64 + t * 16 + gp;
            int col = colBase + warpN * 64 + j * 8 + 2 * tig;
            float2 r0, r1;
            r0.x = acc[t][j][0]; r0.y = acc[t][j][1];
            r1.x = acc[t][j][2]; r1.y = acc[t][j][3];
            *(float2*)&Cb[(size_t)row * SEQ + col] = r0;
            *(float2*)&Cb[(size_t)(row + 8) * SEQ + col] = r1;
        }
    }
}

// ---------------------------------------------------------------------------
// Softmax over one 2048-wide row per block, in-place.
// ---------------------------------------------------------------------------
__global__ __launch_bounds__(256) void softmax_kernel(float* __restrict__ attn)
{
    const int tid = threadIdx.x;
    float* p = attn + (size_t)blockIdx.x * SEQ;
    float4 v0 = ((const float4*)p)[tid];
    float4 v1 = ((const float4*)p)[tid + 256];

    float m = fmaxf(fmaxf(fmaxf(v0.x, v0.y), fmaxf(v0.z, v0.w)),
                    fmaxf(fmaxf(v1.x, v1.y), fmaxf(v1.z, v1.w)));
    __shared__ float red[8];
#pragma unroll
    for (int o = 16; o > 0; o >>= 1) m = fmaxf(m, __shfl_xor_sync(0xffffffffu, m, o));
    if ((tid & 31) == 0) red[tid >> 5] = m;
    __syncthreads();
    m = fmaxf(fmaxf(fmaxf(red[0], red[1]), fmaxf(red[2], red[3])),
              fmaxf(fmaxf(red[4], red[5]), fmaxf(red[6], red[7])));
    __syncthreads();

    float e[8];
    e[0] = expf(v0.x - m); e[1] = expf(v0.y - m);
    e[2] = expf(v0.z - m); e[3] = expf(v0.w - m);
    e[4] = expf(v1.x - m); e[5] = expf(v1.y - m);
    e[6] = expf(v1.z - m); e[7] = expf(v1.w - m);
    float s = ((e[0] + e[1]) + (e[2] + e[3])) + ((e[4] + e[5]) + (e[6] + e[7]));
#pragma unroll
    for (int o = 16; o > 0; o >>= 1) s += __shfl_xor_sync(0xffffffffu, s, o);
    if ((tid & 31) == 0) red[tid >> 5] = s;
    __syncthreads();
    s = ((red[0] + red[1]) + (red[2] + red[3])) + ((red[4] + red[5]) + (red[6] + red[7]));
    float inv = 1.0f / s;

    float4 w0, w1;
    w0.x = e[0] * inv; w0.y = e[1] * inv; w0.z = e[2] * inv; w0.w = e[3] * inv;
    w1.x = e[4] * inv; w1.y = e[5] * inv; w1.z = e[6] * inv; w1.w = e[7] * inv;
    ((float4*)p)[tid] = w0;
    ((float4*)p)[tid + 256] = w1;
}

// ---------------------------------------------------------------------------
// ctx = attn @ V per (b,h): [2048,2048]@[2048,64]. CTA 128x64, warp 64x32,
// BK=16 double-buffered.
// ---------------------------------------------------------------------------
__global__ __launch_bounds__(128) void ctx_tf32(const float* __restrict__ attn)
{
    __shared__ uint32_t Ps[2][128][20];
    __shared__ uint32_t Vs[2][16][72];   // [k][n], stride 72 == 8 mod 32

    const int tid = threadIdx.x;
    const int lane = tid & 31, wid = tid >> 5;
    const int warpM = wid >> 1, warpN = wid & 1;
    const int gp = lane >> 2, tig = lane & 3;
    const int z = blockIdx.y, b = z >> 4, h = z & 15;
    const int rowBase = blockIdx.x * 128;

    const float* pRow = attn + (size_t)z * SEQ * SEQ + (size_t)(rowBase + tid) * SEQ;
    const float* Vb = g_v + (size_t)b * SEQ * DMODEL + h * HD;
    const int vkk = tid >> 4, vn4 = tid & 15;

    float4 pR[4], vR[2];
#pragma unroll
    for (int i = 0; i < 4; i++) pR[i] = *(const float4*)(pRow + i * 4);
#pragma unroll
    for (int i = 0; i < 2; i++)
        vR[i] = *(const float4*)(Vb + (size_t)(vkk + i * 8) * DMODEL + vn4 * 4);

    float acc[4][4][4];
#pragma unroll
    for (int t = 0; t < 4; t++)
#pragma unroll
        for (int j = 0; j < 4; j++)
#pragma unroll
            for (int q = 0; q < 4; q++) acc[t][j][q] = 0.0f;

#pragma unroll
    for (int i = 0; i < 4; i++) {
        uint32_t* pp = &Ps[0][tid][i * 4];
        pp[0] = f2tf(pR[i].x); pp[1] = f2tf(pR[i].y);
        pp[2] = f2tf(pR[i].z); pp[3] = f2tf(pR[i].w);
    }
#pragma unroll
    for (int i = 0; i < 2; i++) {
        uint32_t* vp = &Vs[0][vkk + i * 8][vn4 * 4];
        vp[0] = f2tf(vR[i].x); vp[1] = f2tf(vR[i].y);
        vp[2] = f2tf(vR[i].z); vp[3] = f2tf(vR[i].w);
    }
    __syncthreads();

    const int KT = SEQ / 16;   // 128
    for (int kt = 0; kt < KT; ++kt) {
        const int buf = kt & 1;
        if (kt + 1 < KT) {
            const int k0 = (kt + 1) * 16;
#pragma unroll
            for (int i = 0; i < 4; i++) pR[i] = *(const float4*)(pRow + k0 + i * 4);
#pragma unroll
            for (int i = 0; i < 2; i++)
                vR[i] = *(const float4*)(Vb + (size_t)(k0 + vkk + i * 8) * DMODEL + vn4 * 4);
        }

#pragma unroll
        for (int ks = 0; ks < 2; ++ks) {
            uint32_t a[4][4], bfr[4][2];
#pragma unroll
            for (int t = 0; t < 4; t++) {
                int r = warpM * 64 + t * 16 + gp;
                a[t][0] = Ps[buf][r][ks * 8 + tig];
                a[t][1] = Ps[buf][r + 8][ks * 8 + tig];
                a[t][2] = Ps[buf][r][ks * 8 + tig + 4];
                a[t][3] = Ps[buf][r + 8][ks * 8 + tig + 4];
            }
#pragma unroll
            for (int j = 0; j < 4; j++) {
                int n = warpN * 32 + j * 8 + gp;
                bfr[j][0] = Vs[buf][ks * 8 + tig][n];
                bfr[j][1] = Vs[buf][ks * 8 + tig + 4][n];
            }
#pragma unroll
            for (int t = 0; t < 4; t++)
#pragma unroll
                for (int j = 0; j < 4; j++)
                    mma8(acc[t][j], a[t], bfr[j]);
        }

        if (kt + 1 < KT) {
            const int nb = buf ^ 1;
#pragma unroll
            for (int i = 0; i < 4; i++) {
                uint32_t* pp = &Ps[nb][tid][i * 4];
                pp[0] = f2tf(pR[i].x); pp[1] = f2tf(pR[i].y);
                pp[2] = f2tf(pR[i].z); pp[3] = f2tf(pR[i].w);
            }
#pragma unroll
            for (int i = 0; i < 2; i++) {
                uint32_t* vp = &Vs[nb][vkk + i * 8][vn4 * 4];
                vp[0] = f2tf(vR[i].x); vp[1] = f2tf(vR[i].y);
                vp[2] = f2tf(vR[i].z); vp[3] = f2tf(vR[i].w);
            }
        }
        __syncthreads();
    }

#pragma unroll
    for (int t = 0; t < 4; t++) {
#pragma unroll
        for (int j = 0; j < 4; j++) {
            int row = rowBase + warpM * 64 + t * 16 + gp;
            int col = warpN * 32 + j * 8 + 2 * tig;
            float* dst0 = g_ctx + (size_t)(b * SEQ + row) * DMODEL + h * HD + col;
            float* dst1 = g_ctx + (size_t)(b * SEQ + row + 8) * DMODEL + h * HD + col;
            float2 r0, r1;
            r0.x = acc[t][j][0]; r0.y = acc[t][j][1];
            r1.x = acc[t][j][2]; r1.y = acc[t][j][3];
            *(float2*)dst0 = r0;
            *(float2*)dst1 = r1;
        }
    }
}

// ---------------------------------------------------------------------------
extern "C" void kernel_launch(void* const* d_in, const int* in_sizes, int n_in,
                              void* d_out, int out_size)
{
    const float* inputs_q  = (const float*)d_in[0];
    const float* inputs_kv = (const float*)d_in[1];
    const float* Wq = (const float*)d_in[2];
    const float* bq = (const float*)d_in[3];
    const float* Wk = (const float*)d_in[4];
    const float* bk = (const float*)d_in[5];
    const float* Wv = (const float*)d_in[6];
    const float* bv = (const float*)d_in[7];
    const float* Wo = (const float*)d_in[8];
    const float* bo = (const float*)d_in[9];

    float* out  = (float*)d_out;                       // [B,SQ,D]
    float* attn = out + (size_t)BB * SEQ * DMODEL;     // [B,H,SQ,SKV]

    float *q, *k, *v, *ctx;
    cudaGetSymbolAddress((void**)&q,   g_q);
    cudaGetSymbolAddress((void**)&k,   g_k);
    cudaGetSymbolAddress((void**)&v,   g_v);
    cudaGetSymbolAddress((void**)&ctx, g_ctx);

    dim3 gProj(DMODEL / 128, (BB * SEQ) / 128);        // (8, 32)

    proj_tf32<<<gProj, 128>>>(inputs_q,  Wq, bq, q, BB * SEQ, DMODEL, DMODEL);
    proj_tf32<<<gProj, 128>>>(inputs_kv, Wk, bk, k, BB * SEQ, DMODEL, DMODEL);
    proj_tf32<<<gProj, 128>>>(inputs_kv, Wv, bv, v, BB * SEQ, DMODEL, DMODEL);

    scores_tf32<<<dim3(SEQ / 128, SEQ / 128, BB * NH), 128>>>(attn);

    softmax_kernel<<<BB * NH * SEQ, 256>>>(attn);

    ctx_tf32<<<dim3(SEQ / 128, BB * NH), 128>>>(attn);

    proj_tf32<<<gProj, 128>>>(ctx, Wo, bo, out, BB * SEQ, DMODEL, DMODEL);
}